// round 12
// baseline (speedup 1.0000x reference)
#include <cuda_runtime.h>
#include <cuda_fp16.h>
#include <cstdint>

// Single-term fp16 GEMM over compacted valid tokens; surplus GEMM CTAs
// zero the invalid output rows (no separate zero kernel).
//
// Problem constants
#define TOKENS       12800
#define K_DIM        1152
#define D_SEM_DIM    768
#define D_PROMPT_DIM 384
#define N_DIM        2048
#define NUM_ITEMS_C  100000

// GEMM tiling
#define BM      128
#define BN      256
#define BK      64
#define NSLAB   (K_DIM / BK)               // 18
#define STAGES  4

#define A_BYTES     (BM * BK * 2)          // 16384 (row stride 128 B)
#define B_BYTES     (BN * BK * 2)          // 32768
#define STAGE_BYTES (A_BYTES + B_BYTES)    // 49152
#define SMEM_TOTAL  (STAGES * STAGE_BYTES) // 196608

// fp16 operands: A gathered+compacted, W converted
__device__ __align__(256) __half g_Ah[(size_t)TOKENS * K_DIM];
__device__ __align__(256) __half g_Wh[(size_t)N_DIM * K_DIM];
// compaction state
__device__ int g_count;          // # valid tokens
__device__ int g_icount;         // # invalid tokens
__device__ int g_slot[TOKENS];   // orig token -> compacted slot (-1 invalid)
__device__ int g_c2o[TOKENS];    // compacted slot -> orig token
__device__ int g_inv[TOKENS];    // invalid list -> orig token

// ---------------- helpers ----------------
__device__ __forceinline__ uint32_t smem_u32_of(const void* p) {
    uint32_t a;
    asm("{ .reg .u64 t; cvta.to.shared.u64 t, %1; cvt.u32.u64 %0, t; }" : "=r"(a) : "l"(p));
    return a;
}
__device__ __forceinline__ void cp16(uint32_t dst, const void* src) {
    asm volatile("cp.async.cg.shared.global [%0], [%1], 16;" :: "r"(dst), "l"(src) : "memory");
}
__device__ __forceinline__ void ldsm4(uint32_t* r, uint32_t addr) {
    asm volatile("ldmatrix.sync.aligned.m8n8.x4.shared.b16 {%0,%1,%2,%3}, [%4];"
                 : "=r"(r[0]), "=r"(r[1]), "=r"(r[2]), "=r"(r[3]) : "r"(addr));
}
__device__ __forceinline__ void mma16816(float* d, const uint32_t* a, const uint32_t* b) {
    asm volatile(
        "mma.sync.aligned.m16n8k16.row.col.f32.f16.f16.f32 "
        "{%0,%1,%2,%3}, {%4,%5,%6,%7}, {%8,%9}, {%0,%1,%2,%3};"
        : "+f"(d[0]), "+f"(d[1]), "+f"(d[2]), "+f"(d[3])
        : "r"(a[0]), "r"(a[1]), "r"(a[2]), "r"(a[3]), "r"(b[0]), "r"(b[1]));
}
// 128B-row swizzle: chunk' = c ^ (row & 7); every ldmatrix 8-row phase hits
// 8 distinct 16B banks.
__device__ __forceinline__ uint32_t chswz(int row, int c) {
    return (uint32_t)(row * 128 + ((c ^ (row & 7)) << 4));
}

// load one K-slab (A 128x64, W 256x64 fp16) into a pipeline stage
__device__ __forceinline__ void load_slab(uint32_t smem_u32, int stage, int s,
                                          int i0, int n0, int tid) {
    const int kk = s * BK;
    const uint32_t stA = smem_u32 + stage * STAGE_BYTES;
    const uint32_t stB = stA + A_BYTES;
    #pragma unroll
    for (int i = 0; i < 4; i++) {                        // A: 1024 chunks of 16B
        int j = tid + 256 * i, r = j >> 3, c = j & 7;
        cp16(stA + chswz(r, c), g_Ah + (size_t)(i0 + r) * K_DIM + kk + c * 8);
    }
    #pragma unroll
    for (int i = 0; i < 8; i++) {                        // W: 2048 chunks
        int j = tid + 256 * i, r = j >> 3, c = j & 7;
        cp16(stB + chswz(r, c), g_Wh + (size_t)(n0 + r) * K_DIM + kk + c * 8);
    }
    asm volatile("cp.async.commit_group;" ::: "memory");
}

// ---------------- GEMM kernel (+ invalid-row zeroing on surplus tiles) ----
__global__ __launch_bounds__(256, 1)
void gemm_kernel(float* __restrict__ out)
{
    const int n_valid  = g_count;
    const int nv_tiles = (n_valid + BM - 1) / BM;
    const int tid = threadIdx.x;
    const int lid = tid & 31;
    const int n0  = blockIdx.x * BN;

    if ((int)blockIdx.y >= nv_tiles) {
        // surplus tile: zero invalid original rows for this BN column slice.
        // grid.y = 101 guarantees (grid.y - nv_tiles)*BM >= n_invalid.
        const int yr = blockIdx.y - nv_tiles;
        const int n_invalid = TOKENS - n_valid;
        const float4 z = make_float4(0.f, 0.f, 0.f, 0.f);
        const int wid = tid >> 5;
        #pragma unroll
        for (int j = wid; j < BM; j += 8) {         // one warp per row
            int inv = yr * BM + j;
            if (inv < n_invalid) {
                float* p = out + (size_t)g_inv[inv] * N_DIM + n0 + lid * 8;
                *(float4*)p       = z;
                *(float4*)(p + 4) = z;
            }
        }
        return;
    }

    const int i0 = blockIdx.y * BM;      // compacted-row tile start
    extern __shared__ char smem[];
    const uint32_t smem_u32 = smem_u32_of(smem);
    const int wid = tid >> 5;
    const int wm  = wid >> 2;            // 0..1 (64-row slab)
    const int wn  = wid & 3;             // 0..3 (64-col slab)

    __shared__ int s_orig[BM];
    if (tid < BM)
        s_orig[tid] = (i0 + tid < n_valid) ? g_c2o[i0 + tid] : -1;

    float acc[4][8][4];
    #pragma unroll
    for (int mf = 0; mf < 4; mf++)
        #pragma unroll
        for (int nf = 0; nf < 8; nf++)
            #pragma unroll
            for (int q = 0; q < 4; q++) acc[mf][nf][q] = 0.f;

    // prologue: stages 0..2
    load_slab(smem_u32, 0, 0, i0, n0, tid);
    load_slab(smem_u32, 1, 1, i0, n0, tid);
    load_slab(smem_u32, 2, 2, i0, n0, tid);

    for (int s = 0; s < NSLAB; ++s) {
        if (s < NSLAB - 2)      asm volatile("cp.async.wait_group 2;" ::: "memory");
        else if (s < NSLAB - 1) asm volatile("cp.async.wait_group 1;" ::: "memory");
        else                    asm volatile("cp.async.wait_group 0;" ::: "memory");
        __syncthreads();

        if (s + 3 < NSLAB)
            load_slab(smem_u32, (s + 3) & 3, s + 3, i0, n0, tid);

        const uint32_t stA = smem_u32 + (s & 3) * STAGE_BYTES;
        const uint32_t stB = stA + A_BYTES;

        #pragma unroll
        for (int kf = 0; kf < 4; kf++) {
            uint32_t a[4][4], b[4][4];
            #pragma unroll
            for (int mf = 0; mf < 4; mf++) {
                int row = wm * 64 + mf * 16 + (lid & 7) + ((lid >> 3) & 1) * 8;
                int ch  = 2 * kf + (lid >> 4);
                ldsm4(a[mf], stA + chswz(row, ch));
            }
            #pragma unroll
            for (int p = 0; p < 4; p++) {
                int row = wn * 64 + p * 16 + (lid & 7) + (lid >> 4) * 8;
                int ch  = 2 * kf + ((lid >> 3) & 1);
                ldsm4(b[p], stB + chswz(row, ch));
            }
            #pragma unroll
            for (int mf = 0; mf < 4; mf++)
                #pragma unroll
                for (int nf = 0; nf < 8; nf++)
                    mma16816(acc[mf][nf], a[mf], &b[nf >> 1][(nf & 1) * 2]);
        }
    }
    __syncthreads();

    // epilogue: scatter compacted rows back to original token rows
    const int g = lid >> 2, t = lid & 3;
    #pragma unroll
    for (int mf = 0; mf < 4; mf++) {
        const int r0 = wm * 64 + mf * 16 + g;
        const int o0 = s_orig[r0];
        const int o1 = s_orig[r0 + 8];
        #pragma unroll
        for (int nf = 0; nf < 8; nf++) {
            const int col = n0 + wn * 64 + nf * 8 + t * 2;
            if (o0 >= 0)
                *(float2*)&out[(size_t)o0 * N_DIM + col] =
                    make_float2(acc[mf][nf][0], acc[mf][nf][1]);
            if (o1 >= 0)
                *(float2*)&out[(size_t)o1 * N_DIM + col] =
                    make_float2(acc[mf][nf][2], acc[mf][nf][3]);
        }
    }
}

// ---------------- pre-pass kernels ----------------
__device__ __forceinline__ void cvt4_store(float4 x, __half* ph) {
    union { __half b[4]; uint2 u; } uh;
    uh.b[0] = __float2half(x.x); uh.b[1] = __float2half(x.y);
    uh.b[2] = __float2half(x.z); uh.b[3] = __float2half(x.w);
    *(uint2*)ph = uh.u;
}

__global__ void convert_w_kernel(const float* __restrict__ W) {
    if (blockIdx.x == 0 && threadIdx.x == 0) { g_count = 0; g_icount = 0; }
    const int n = blockIdx.x;
    const int k = threadIdx.x * 4;              // 288 threads cover K=1152
    const size_t o = (size_t)n * K_DIM + k;
    cvt4_store(*(const float4*)&W[o], g_Wh + o);
}

// assign compacted slots + invalid list + write amask / tok_item_ids
__global__ void compact_kernel(const int* __restrict__ ids, float* __restrict__ out) {
    int i = blockIdx.x * 256 + threadIdx.x;
    if (i >= TOKENS) return;
    int id = ids[i];
    bool valid = (id >= 0 && id < NUM_ITEMS_C);
    const size_t base = (size_t)TOKENS * N_DIM;
    out[base + i]          = valid ? 1.0f : 0.0f;
    out[base + TOKENS + i] = valid ? (float)id : -1.0f;
    if (valid) {
        int s = atomicAdd(&g_count, 1);
        g_slot[i] = s;
        g_c2o[s] = i;
    } else {
        g_slot[i] = -1;
        int s = atomicAdd(&g_icount, 1);
        g_inv[s] = i;
    }
}

// gather valid tokens into compacted rows, fp16
__global__ void gather_kernel(const int* __restrict__ ids,
                              const float* __restrict__ E,
                              const float* __restrict__ V) {
    const int i = blockIdx.x;
    const int slot = g_slot[i];
    if (slot < 0) return;
    const int k = threadIdx.x * 4;
    const int id = ids[i];
    float4 x = (k < D_SEM_DIM)
        ? *(const float4*)&E[(size_t)id * D_SEM_DIM + k]
        : *(const float4*)&V[(size_t)id * D_PROMPT_DIM + (k - D_SEM_DIM)];
    cvt4_store(x, g_Ah + (size_t)slot * K_DIM + k);
}

extern "C" void kernel_launch(void* const* d_in, const int* in_sizes, int n_in,
                              void* d_out, int out_size)
{
    const int*   ids      = (const int*)  d_in[0];
    const float* E_sem    = (const float*)d_in[2];
    const float* v_prompt = (const float*)d_in[3];
    const float* W        = (const float*)d_in[4];
    float*       out      = (float*)d_out;

    static bool attr_set = false;
    if (!attr_set) {
        cudaFuncSetAttribute(gemm_kernel, cudaFuncAttributeMaxDynamicSharedMemorySize, SMEM_TOTAL);
        attr_set = true;
    }

    convert_w_kernel<<<N_DIM, 288>>>(W);                         // also resets counters
    compact_kernel<<<(TOKENS + 255) / 256, 256>>>(ids, out);     // slots + inv list + amask/tok
    gather_kernel<<<TOKENS, 288>>>(ids, E_sem, v_prompt);        // compacted fp16 A
    dim3 grid(N_DIM / BN, TOKENS / BM + 1);                      // (8, 101): valid tiles GEMM,
    gemm_kernel<<<grid, 256, SMEM_TOTAL>>>(out);                 // surplus tiles zero invalid rows
}

// round 13
// speedup vs baseline: 1.0509x; 1.0509x over previous
#include <cuda_runtime.h>
#include <cuda_fp16.h>
#include <cstdint>

// Single-term fp16 GEMM over compacted valid tokens; surplus GEMM CTAs
// zero the invalid output rows. 512 threads / 16 warps, 64x32 warp tiles.
//
// Problem constants
#define TOKENS       12800
#define K_DIM        1152
#define D_SEM_DIM    768
#define D_PROMPT_DIM 384
#define N_DIM        2048
#define NUM_ITEMS_C  100000

// GEMM tiling
#define BM      128
#define BN      256
#define BK      64
#define NSLAB   (K_DIM / BK)               // 18
#define STAGES  4
#define NTHREADS 512

#define A_BYTES     (BM * BK * 2)          // 16384 (row stride 128 B)
#define B_BYTES     (BN * BK * 2)          // 32768
#define STAGE_BYTES (A_BYTES + B_BYTES)    // 49152
#define SMEM_TOTAL  (STAGES * STAGE_BYTES) // 196608

// fp16 operands: A gathered+compacted, W converted
__device__ __align__(256) __half g_Ah[(size_t)TOKENS * K_DIM];
__device__ __align__(256) __half g_Wh[(size_t)N_DIM * K_DIM];
// compaction state
__device__ int g_count;          // # valid tokens
__device__ int g_icount;         // # invalid tokens
__device__ int g_slot[TOKENS];   // orig token -> compacted slot (-1 invalid)
__device__ int g_c2o[TOKENS];    // compacted slot -> orig token
__device__ int g_inv[TOKENS];    // invalid list -> orig token

// ---------------- helpers ----------------
__device__ __forceinline__ uint32_t smem_u32_of(const void* p) {
    uint32_t a;
    asm("{ .reg .u64 t; cvta.to.shared.u64 t, %1; cvt.u32.u64 %0, t; }" : "=r"(a) : "l"(p));
    return a;
}
__device__ __forceinline__ void cp16(uint32_t dst, const void* src) {
    asm volatile("cp.async.cg.shared.global [%0], [%1], 16;" :: "r"(dst), "l"(src) : "memory");
}
__device__ __forceinline__ void ldsm4(uint32_t* r, uint32_t addr) {
    asm volatile("ldmatrix.sync.aligned.m8n8.x4.shared.b16 {%0,%1,%2,%3}, [%4];"
                 : "=r"(r[0]), "=r"(r[1]), "=r"(r[2]), "=r"(r[3]) : "r"(addr));
}
__device__ __forceinline__ void mma16816(float* d, const uint32_t* a, const uint32_t* b) {
    asm volatile(
        "mma.sync.aligned.m16n8k16.row.col.f32.f16.f16.f32 "
        "{%0,%1,%2,%3}, {%4,%5,%6,%7}, {%8,%9}, {%0,%1,%2,%3};"
        : "+f"(d[0]), "+f"(d[1]), "+f"(d[2]), "+f"(d[3])
        : "r"(a[0]), "r"(a[1]), "r"(a[2]), "r"(a[3]), "r"(b[0]), "r"(b[1]));
}
// 128B-row swizzle: chunk' = c ^ (row & 7); every ldmatrix 8-row phase hits
// 8 distinct 16B banks.
__device__ __forceinline__ uint32_t chswz(int row, int c) {
    return (uint32_t)(row * 128 + ((c ^ (row & 7)) << 4));
}

// load one K-slab (A 128x64, W 256x64 fp16) into a pipeline stage
__device__ __forceinline__ void load_slab(uint32_t smem_u32, int stage, int s,
                                          int i0, int n0, int tid) {
    const int kk = s * BK;
    const uint32_t stA = smem_u32 + stage * STAGE_BYTES;
    const uint32_t stB = stA + A_BYTES;
    #pragma unroll
    for (int i = 0; i < 2; i++) {                        // A: 1024 chunks of 16B
        int j = tid + NTHREADS * i, r = j >> 3, c = j & 7;
        cp16(stA + chswz(r, c), g_Ah + (size_t)(i0 + r) * K_DIM + kk + c * 8);
    }
    #pragma unroll
    for (int i = 0; i < 4; i++) {                        // W: 2048 chunks
        int j = tid + NTHREADS * i, r = j >> 3, c = j & 7;
        cp16(stB + chswz(r, c), g_Wh + (size_t)(n0 + r) * K_DIM + kk + c * 8);
    }
    asm volatile("cp.async.commit_group;" ::: "memory");
}

// ---------------- GEMM kernel (+ invalid-row zeroing on surplus tiles) ----
__global__ __launch_bounds__(NTHREADS, 1)
void gemm_kernel(float* __restrict__ out)
{
    const int n_valid  = g_count;
    const int nv_tiles = (n_valid + BM - 1) / BM;
    const int tid = threadIdx.x;
    const int lid = tid & 31;
    const int wid = tid >> 5;
    const int n0  = blockIdx.x * BN;

    if ((int)blockIdx.y >= nv_tiles) {
        // surplus tile: zero invalid original rows for this BN column slice.
        const int yr = blockIdx.y - nv_tiles;
        const int n_invalid = TOKENS - n_valid;
        const float4 z = make_float4(0.f, 0.f, 0.f, 0.f);
        #pragma unroll
        for (int j = wid; j < BM; j += 16) {        // one warp per row
            int inv = yr * BM + j;
            if (inv < n_invalid) {
                float* p = out + (size_t)g_inv[inv] * N_DIM + n0 + lid * 8;
                *(float4*)p       = z;
                *(float4*)(p + 4) = z;
            }
        }
        return;
    }

    const int i0 = blockIdx.y * BM;      // compacted-row tile start
    extern __shared__ char smem[];
    const uint32_t smem_u32 = smem_u32_of(smem);
    const int wm  = wid >> 3;            // 0..1 (64-row slab)
    const int wn  = wid & 7;             // 0..7 (32-col slab)

    __shared__ int s_orig[BM];
    if (tid < BM)
        s_orig[tid] = (i0 + tid < n_valid) ? g_c2o[i0 + tid] : -1;

    float acc[4][4][4];
    #pragma unroll
    for (int mf = 0; mf < 4; mf++)
        #pragma unroll
        for (int nf = 0; nf < 4; nf++)
            #pragma unroll
            for (int q = 0; q < 4; q++) acc[mf][nf][q] = 0.f;

    // prologue: stages 0..2
    load_slab(smem_u32, 0, 0, i0, n0, tid);
    load_slab(smem_u32, 1, 1, i0, n0, tid);
    load_slab(smem_u32, 2, 2, i0, n0, tid);

    for (int s = 0; s < NSLAB; ++s) {
        if (s < NSLAB - 2)      asm volatile("cp.async.wait_group 2;" ::: "memory");
        else if (s < NSLAB - 1) asm volatile("cp.async.wait_group 1;" ::: "memory");
        else                    asm volatile("cp.async.wait_group 0;" ::: "memory");
        __syncthreads();

        if (s + 3 < NSLAB)
            load_slab(smem_u32, (s + 3) & 3, s + 3, i0, n0, tid);

        const uint32_t stA = smem_u32 + (s & 3) * STAGE_BYTES;
        const uint32_t stB = stA + A_BYTES;

        #pragma unroll
        for (int kf = 0; kf < 4; kf++) {
            uint32_t a[4][4], b[2][4];
            #pragma unroll
            for (int mf = 0; mf < 4; mf++) {
                int row = wm * 64 + mf * 16 + (lid & 7) + ((lid >> 3) & 1) * 8;
                int ch  = 2 * kf + (lid >> 4);
                ldsm4(a[mf], stA + chswz(row, ch));
            }
            #pragma unroll
            for (int p = 0; p < 2; p++) {
                int row = wn * 32 + p * 16 + (lid & 7) + (lid >> 4) * 8;
                int ch  = 2 * kf + ((lid >> 3) & 1);
                ldsm4(b[p], stB + chswz(row, ch));
            }
            #pragma unroll
            for (int mf = 0; mf < 4; mf++)
                #pragma unroll
                for (int nf = 0; nf < 4; nf++)
                    mma16816(acc[mf][nf], a[mf], &b[nf >> 1][(nf & 1) * 2]);
        }
    }
    __syncthreads();

    // epilogue: scatter compacted rows back to original token rows
    const int g = lid >> 2, t = lid & 3;
    #pragma unroll
    for (int mf = 0; mf < 4; mf++) {
        const int r0 = wm * 64 + mf * 16 + g;
        const int o0 = s_orig[r0];
        const int o1 = s_orig[r0 + 8];
        #pragma unroll
        for (int nf = 0; nf < 4; nf++) {
            const int col = n0 + wn * 32 + nf * 8 + t * 2;
            if (o0 >= 0)
                *(float2*)&out[(size_t)o0 * N_DIM + col] =
                    make_float2(acc[mf][nf][0], acc[mf][nf][1]);
            if (o1 >= 0)
                *(float2*)&out[(size_t)o1 * N_DIM + col] =
                    make_float2(acc[mf][nf][2], acc[mf][nf][3]);
        }
    }
}

// ---------------- pre-pass kernels ----------------
__device__ __forceinline__ void cvt4_store(float4 x, __half* ph) {
    union { __half b[4]; uint2 u; } uh;
    uh.b[0] = __float2half(x.x); uh.b[1] = __float2half(x.y);
    uh.b[2] = __float2half(x.z); uh.b[3] = __float2half(x.w);
    *(uint2*)ph = uh.u;
}

__global__ void convert_w_kernel(const float* __restrict__ W) {
    if (blockIdx.x == 0 && threadIdx.x == 0) { g_count = 0; g_icount = 0; }
    const int n = blockIdx.x;
    const int k = threadIdx.x * 4;              // 288 threads cover K=1152
    const size_t o = (size_t)n * K_DIM + k;
    cvt4_store(*(const float4*)&W[o], g_Wh + o);
}

// assign compacted slots + invalid list + write amask / tok_item_ids
__global__ void compact_kernel(const int* __restrict__ ids, float* __restrict__ out) {
    int i = blockIdx.x * 256 + threadIdx.x;
    if (i >= TOKENS) return;
    int id = ids[i];
    bool valid = (id >= 0 && id < NUM_ITEMS_C);
    const size_t base = (size_t)TOKENS * N_DIM;
    out[base + i]          = valid ? 1.0f : 0.0f;
    out[base + TOKENS + i] = valid ? (float)id : -1.0f;
    if (valid) {
        int s = atomicAdd(&g_count, 1);
        g_slot[i] = s;
        g_c2o[s] = i;
    } else {
        g_slot[i] = -1;
        int s = atomicAdd(&g_icount, 1);
        g_inv[s] = i;
    }
}

// gather valid tokens into compacted rows, fp16
__global__ void gather_kernel(const int* __restrict__ ids,
                              const float* __restrict__ E,
                              const float* __restrict__ V) {
    const int i = blockIdx.x;
    const int slot = g_slot[i];
    if (slot < 0) return;
    const int k = threadIdx.x * 4;
    const int id = ids[i];
    float4 x = (k < D_SEM_DIM)
        ? *(const float4*)&E[(size_t)id * D_SEM_DIM + k]
        : *(const float4*)&V[(size_t)id * D_PROMPT_DIM + (k - D_SEM_DIM)];
    cvt4_store(x, g_Ah + (size_t)slot * K_DIM + k);
}

extern "C" void kernel_launch(void* const* d_in, const int* in_sizes, int n_in,
                              void* d_out, int out_size)
{
    const int*   ids      = (const int*)  d_in[0];
    const float* E_sem    = (const float*)d_in[2];
    const float* v_prompt = (const float*)d_in[3];
    const float* W        = (const float*)d_in[4];
    float*       out      = (float*)d_out;

    static bool attr_set = false;
    if (!attr_set) {
        cudaFuncSetAttribute(gemm_kernel, cudaFuncAttributeMaxDynamicSharedMemorySize, SMEM_TOTAL);
        attr_set = true;
    }

    convert_w_kernel<<<N_DIM, 288>>>(W);                         // also resets counters
    compact_kernel<<<(TOKENS + 255) / 256, 256>>>(ids, out);     // slots + inv list + amask/tok
    gather_kernel<<<TOKENS, 288>>>(ids, E_sem, v_prompt);        // compacted fp16 A
    dim3 grid(N_DIM / BN, TOKENS / BM + 1);                      // (8, 101): valid tiles GEMM,
    gemm_kernel<<<grid, NTHREADS, SMEM_TOTAL>>>(out);            // surplus tiles zero invalid rows
}